// round 15
// baseline (speedup 1.0000x reference)
#include <cuda_runtime.h>
#include <cuda_fp16.h>
#include <cstdint>
#include <cstddef>

// ---------------- problem constants ----------------
#define IN_F      512
#define OUT_F     512
#define B_ROWS    16384
#define NUM_BASIS 10
#define NFEAT     19                  // 1 silu + 8 spline + 10 logistic
#define KTOT      (NFEAT * IN_F)      // 9728

// ---------------- GEMM tiling ----------------
#define BM 128
#define BN 128
#define BK 64
#define NC (KTOT / BK)                // 152
#define STAGES 3
#define TILE_BYTES (BM * BK * 2)      // 16384 (A or B tile, fp16)
#define STAGE_BYTES (2 * TILE_BYTES)  // 32768
#define SMEM_TOTAL (STAGES * STAGE_BYTES)  // 98304

// ---------------- scratch (device globals; no allocation) ----------------
__device__ __align__(1024) __half g_F[(size_t)B_ROWS * KTOT];   // 318 MB
__device__ __align__(1024) __half g_W[(size_t)OUT_F * KTOT];    // 10 MB
__device__ __align__(16) float g_tc1[NUM_BASIS * IN_F];         // 0.5*a        [n][i]
__device__ __align__(16) float g_tc2[NUM_BASIS * IN_F];         // -0.5*a*b     [n][i]

// ---------------- PTX helpers ----------------
__device__ __forceinline__ uint32_t smem_u32(const void* p) {
    uint32_t a;
    asm("{ .reg .u64 t; cvta.to.shared.u64 t, %1; cvt.u32.u64 %0, t; }" : "=r"(a) : "l"(p));
    return a;
}
__device__ __forceinline__ void cp_async16(uint32_t dst, const void* src) {
    asm volatile("cp.async.cg.shared.global [%0], [%1], 16;" :: "r"(dst), "l"(src) : "memory");
}
__device__ __forceinline__ void cp_commit() {
    asm volatile("cp.async.commit_group;" ::: "memory");
}
template <int N>
__device__ __forceinline__ void cp_wait() {
    asm volatile("cp.async.wait_group %0;" :: "n"(N) : "memory");
}
__device__ __forceinline__ void ldmatrix_x4(uint32_t* r, uint32_t addr) {
    asm volatile("ldmatrix.sync.aligned.m8n8.x4.shared.b16 {%0, %1, %2, %3}, [%4];"
                 : "=r"(r[0]), "=r"(r[1]), "=r"(r[2]), "=r"(r[3]) : "r"(addr));
}
// fp16-accumulate MMA: D(f16x2 x2) = A*B + C(f16x2 x2)
__device__ __forceinline__ void mma_16816_h(uint32_t* d, const uint32_t* a,
                                            uint32_t b0, uint32_t b1) {
    asm volatile(
        "mma.sync.aligned.m16n8k16.row.col.f16.f16.f16.f16 "
        "{%0, %1}, {%2, %3, %4, %5}, {%6, %7}, {%0, %1};"
        : "+r"(d[0]), "+r"(d[1])
        : "r"(a[0]), "r"(a[1]), "r"(a[2]), "r"(a[3]), "r"(b0), "r"(b1));
}
__device__ __forceinline__ float tanhf_approx(float z) {
    float r; asm("tanh.approx.f32 %0, %1;" : "=f"(r) : "f"(z)); return r;
}

// ---------------- tc-table init (tiny; the ONLY producer featgen depends on) ----------------
__global__ void __launch_bounds__(512) tables_kernel(const float* __restrict__ a,
                                                     const float* __restrict__ b) {
    for (int idx = blockIdx.x * 512 + threadIdx.x; idx < IN_F * NUM_BASIS;
         idx += gridDim.x * 512) {
        const int i = idx / NUM_BASIS;      // a,b are [i][n] row-major
        const int n = idx - i * NUM_BASIS;
        const float av = a[idx];
        const float bv = b[idx];
        g_tc1[n * IN_F + i] = 0.5f * av;
        g_tc2[n * IN_F + i] = -0.5f * av * bv;
    }
}

// ---------------- feature generation ----------------
#define FG_ROWS 32
#define SP_STRIDE 36   // halves per thread staging slot

__device__ __forceinline__ void store_quad(__half* p, const float* v) {
    __half2 lo = __floats2half2_rn(v[0], v[1]);
    __half2 hi = __floats2half2_rn(v[2], v[3]);
    uint2 q;
    q.x = *reinterpret_cast<uint32_t*>(&lo);
    q.y = *reinterpret_cast<uint32_t*>(&hi);
    *reinterpret_cast<uint2*>(p) = q;
}

__global__ void __launch_bounds__(256, 4) featgen_kernel(const float* __restrict__ x) {
    __shared__ __half s_sp[256 * SP_STRIDE];   // 18 KB spline scatter staging
    const int tid = threadIdx.x;

    const int iq   = (tid & 127) * 4;   // 4 consecutive input features per thread
    const int rsub = tid >> 7;          // 0..1
    __half* const myslot = s_sp + tid * SP_STRIDE;
    uint2* const myslot8 = reinterpret_cast<uint2*>(myslot);

    for (int rr = 0; rr < FG_ROWS; rr += 2) {
        const int bb = blockIdx.x * FG_ROWS + rr + rsub;
        const float4 xv = *reinterpret_cast<const float4*>(x + (size_t)bb * IN_F + iq);
        float xs[4] = {xv.x, xv.y, xv.z, xv.w};
        __half* dst = g_F + (size_t)bb * KTOT + iq;

        // ---- f = 0 : silu(x) = 0.5x + 0.5x*tanh(0.5x) ----
        {
            float v[4];
#pragma unroll
            for (int l = 0; l < 4; l++) {
                float hx = 0.5f * xs[l];
                v[l] = fmaf(hx, tanhf_approx(hx), hx);
            }
            store_quad(dst, v);
        }

        // ---- f = 1..8 : cubic B-spline bases via smem scatter staging ----
        {
#pragma unroll
            for (int j = 0; j < 8; j++) myslot8[j] = make_uint2(0u, 0u);

#pragma unroll
            for (int l = 0; l < 4; l++) {
                float u  = (xs[l] + 1.0f) * 2.5f;    // (x - GRID_LO)/h
                float fc = floorf(u);
                float t  = u - fc;
                const int c = (int)fc;
                float t2 = t * t, t3 = t2 * t;
                float om = 1.0f - t;
                float w[4];
                w[0] = om * om * om * (1.0f / 6.0f);
                w[1] = 0.5f * t3 - t2 + (2.0f / 3.0f);
                w[2] = ((-0.5f * t + 0.5f) * t + 0.5f) * t + (1.0f / 6.0f);
                w[3] = t3 * (1.0f / 6.0f);
#pragma unroll
                for (int d = 0; d < 4; d++) {
                    const int jj = c + d;
                    if ((unsigned)jj < 8u)
                        myslot[jj * 4 + l] = __float2half_rn(w[d]);
                }
            }
#pragma unroll
            for (int j = 0; j < 8; j++) {
                uint2 q = myslot8[j];
                *reinterpret_cast<uint2*>(dst + (size_t)(1 + j) * IN_F) = q;
            }
        }

        // ---- f = 9..18 : logistic  2*sigmoid(a(x-b)) = 1 + tanh(0.5a*x - 0.5ab) ----
#pragma unroll
        for (int n = 0; n < NUM_BASIS; n++) {
            const float4 c1v = *reinterpret_cast<const float4*>(&g_tc1[n * IN_F + iq]);
            const float4 c2v = *reinterpret_cast<const float4*>(&g_tc2[n * IN_F + iq]);
            float v[4];
            v[0] = 1.0f + tanhf_approx(fmaf(c1v.x, xs[0], c2v.x));
            v[1] = 1.0f + tanhf_approx(fmaf(c1v.y, xs[1], c2v.y));
            v[2] = 1.0f + tanhf_approx(fmaf(c1v.z, xs[2], c2v.z));
            v[3] = 1.0f + tanhf_approx(fmaf(c1v.w, xs[3], c2v.w));
            store_quad(dst + (size_t)(9 + n) * IN_F, v);
        }
    }
}

// ---------------- weight packing (weights only; overlaps featgen on side stream) ----------------
__global__ void __launch_bounds__(512) packw_kernel(const float* __restrict__ bw,
                                                    const float* __restrict__ sw,
                                                    const float* __restrict__ ss,
                                                    const float* __restrict__ lw,
                                                    const float* __restrict__ ls) {
    const int o = blockIdx.x;
    const int i = threadIdx.x;
    const float lsv = ls[o];
    __half* dst = g_W + (size_t)o * KTOT + i;
#pragma unroll
    for (int f = 0; f < NFEAT; f++) {
        float w;
        if (f == 0)
            w = bw[o * IN_F + i];
        else if (f <= 8)
            w = sw[((size_t)(o * IN_F + i)) * 8 + (f - 1)] * ss[o * IN_F + i];
        else
            w = lw[(size_t)o * (IN_F * NUM_BASIS) + i * NUM_BASIS + (f - 9)] * lsv;
        dst[(size_t)f * IN_F] = __float2half_rn(w);
    }
}

// ---------------- GEMM: out[16384,512] = F @ W^T ----------------
// 256 threads / 8 warps, 2x4 layout, 64x32 warp tiles.
// fp16-accumulate MMA; promoted to persistent fp32 every 2 ks (K=32 window).
__device__ __forceinline__ void load_stage_gemm(uint32_t sbase, int c, int tid,
                                                const __half* Asrc, const __half* Bsrc) {
    const int s = c % STAGES;
    const uint32_t ab = sbase + (uint32_t)s * STAGE_BYTES;
    const uint32_t bbuf = ab + TILE_BYTES;
    const int k0 = c * BK;
#pragma unroll
    for (int j = 0; j < 4; j++) {
        const int u = tid + j * 256;          // 1024 16B units per tile
        const int row = u >> 3;
        const int cc = u & 7;
        const uint32_t soff = (uint32_t)row * 128 + (uint32_t)((cc ^ (row & 7)) << 4);
        cp_async16(ab + soff,   Asrc + (size_t)row * KTOT + k0 + cc * 8);
        cp_async16(bbuf + soff, Bsrc + (size_t)row * KTOT + k0 + cc * 8);
    }
    cp_commit();
}

__global__ void __launch_bounds__(256, 2) gemm_kernel(float* __restrict__ out) {
    extern __shared__ __align__(128) char smem_raw[];
    const uint32_t sbase = smem_u32(smem_raw);

    const int tid  = threadIdx.x;
    const int wid  = tid >> 5;
    const int lane = tid & 31;
    const int m0 = blockIdx.y * BM;
    const int n0 = blockIdx.x * BN;
    const int wm = (wid & 1) * 64;     // 2x4 warp layout, 64x32 warp tile
    const int wn = (wid >> 1) * 32;

    const __half* Asrc = g_F + (size_t)m0 * KTOT;
    const __half* Bsrc = g_W + (size_t)n0 * KTOT;

    float acc[4][4][4];          // persistent fp32
    uint32_t acch[4][4][2];      // fp16x2 window accumulators
#pragma unroll
    for (int mt = 0; mt < 4; mt++)
#pragma unroll
        for (int nt = 0; nt < 4; nt++) {
#pragma unroll
            for (int q = 0; q < 4; q++) acc[mt][nt][q] = 0.0f;
            acch[mt][nt][0] = 0u;
            acch[mt][nt][1] = 0u;
        }

    const int a_row_l = lane & 15;
    const int a_ch_l  = lane >> 4;
    const int b_row_l = (lane & 7) + ((lane >> 4) << 3);
    const int b_ch_l  = (lane >> 3) & 1;

    load_stage_gemm(sbase, 0, tid, Asrc, Bsrc);
    load_stage_gemm(sbase, 1, tid, Asrc, Bsrc);

#pragma unroll 1
    for (int c = 0; c < NC; c++) {
        if (c < NC - 1) cp_wait<1>(); else cp_wait<0>();
        __syncthreads();
        if (c + 2 < NC) load_stage_gemm(sbase, c + 2, tid, Asrc, Bsrc);

        const uint32_t abase = sbase + (uint32_t)(c % STAGES) * STAGE_BYTES;
        const uint32_t bbase = abase + TILE_BYTES;

#pragma unroll
        for (int ks = 0; ks < 4; ks++) {
            uint32_t afr[4][4];
#pragma unroll
            for (int mt = 0; mt < 4; mt++) {
                const int row = wm + mt * 16 + a_row_l;
                const int ch = ks * 2 + a_ch_l;
                ldmatrix_x4(afr[mt], abase + (uint32_t)row * 128
                                         + (uint32_t)((ch ^ (row & 7)) << 4));
            }
            uint32_t bfr[2][4];
#pragma unroll
            for (int np = 0; np < 2; np++) {
                const int row = wn + np * 16 + b_row_l;
                const int ch = ks * 2 + b_ch_l;
                ldmatrix_x4(bfr[np], bbase + (uint32_t)row * 128
                                         + (uint32_t)((ch ^ (row & 7)) << 4));
            }
#pragma unroll
            for (int mt = 0; mt < 4; mt++)
#pragma unroll
                for (int nt = 0; nt < 4; nt++)
                    mma_16816_h(acch[mt][nt], afr[mt],
                                bfr[nt >> 1][(nt & 1) * 2 + 0],
                                bfr[nt >> 1][(nt & 1) * 2 + 1]);

            // promote fp16 window accumulators to fp32 every 2 ks (K=32 window)
            if (ks & 1) {
#pragma unroll
                for (int mt = 0; mt < 4; mt++)
#pragma unroll
                    for (int nt = 0; nt < 4; nt++) {
                        float2 lo = __half22float2(
                            *reinterpret_cast<__half2*>(&acch[mt][nt][0]));
                        float2 hi = __half22float2(
                            *reinterpret_cast<__half2*>(&acch[mt][nt][1]));
                        acc[mt][nt][0] += lo.x;
                        acc[mt][nt][1] += lo.y;
                        acc[mt][nt][2] += hi.x;
                        acc[mt][nt][3] += hi.y;
                        acch[mt][nt][0] = 0u;
                        acch[mt][nt][1] = 0u;
                    }
            }
        }
    }

    // epilogue: direct fp32 stores
#pragma unroll
    for (int mt = 0; mt < 4; mt++) {
#pragma unroll
        for (int nt = 0; nt < 4; nt++) {
            const int m = m0 + wm + mt * 16 + (lane >> 2);
            const int n = n0 + wn + nt * 8 + (lane & 3) * 2;
            float2 v0 = make_float2(acc[mt][nt][0], acc[mt][nt][1]);
            float2 v1 = make_float2(acc[mt][nt][2], acc[mt][nt][3]);
            *reinterpret_cast<float2*>(out + (size_t)m * OUT_F + n) = v0;
            *reinterpret_cast<float2*>(out + (size_t)(m + 8) * OUT_F + n) = v1;
        }
    }
}

// ---------------- launch: serial featgen->gemm; packw overlapped with featgen ----------------
extern "C" void kernel_launch(void* const* d_in, const int* in_sizes, int n_in,
                              void* d_out, int out_size) {
    const float* x  = (const float*)d_in[0];
    const float* bw = (const float*)d_in[1];
    const float* sw = (const float*)d_in[2];
    const float* ss = (const float*)d_in[3];
    const float* a  = (const float*)d_in[4];
    const float* b  = (const float*)d_in[5];
    const float* lw = (const float*)d_in[6];
    const float* ls = (const float*)d_in[7];
    float* out = (float*)d_out;

    static cudaStream_t s2 = nullptr;
    static cudaEvent_t ev_fork = nullptr, ev_pw = nullptr;
    if (s2 == nullptr) {
        cudaStreamCreateWithFlags(&s2, cudaStreamNonBlocking);
        cudaEventCreateWithFlags(&ev_fork, cudaEventDisableTiming);
        cudaEventCreateWithFlags(&ev_pw, cudaEventDisableTiming);
        cudaFuncSetAttribute(gemm_kernel, cudaFuncAttributeMaxDynamicSharedMemorySize,
                             SMEM_TOTAL);
    }

    // stream 0: tiny table init (the only thing featgen depends on), then featgen
    tables_kernel<<<10, 512>>>(a, b);
    cudaEventRecord(ev_fork, 0);
    featgen_kernel<<<B_ROWS / FG_ROWS, 256>>>(x);

    // side stream: weight packing, concurrent with featgen (gemm needs it, featgen doesn't)
    cudaStreamWaitEvent(s2, ev_fork, 0);
    packw_kernel<<<OUT_F, 512, 0, s2>>>(bw, sw, ss, lw, ls);
    cudaEventRecord(ev_pw, s2);

    // stream 0: gemm after featgen (program order) AND packw (event)
    cudaStreamWaitEvent(0, ev_pw, 0);
    dim3 grid(OUT_F / BN, B_ROWS / BM);   // x = n (4, fast), y = m (128)
    gemm_kernel<<<grid, 256, SMEM_TOTAL>>>(out);
}

// round 16
// speedup vs baseline: 1.5618x; 1.5618x over previous
#include <cuda_runtime.h>
#include <cuda_fp16.h>
#include <cstdint>
#include <cstddef>

// ---------------- problem constants ----------------
#define IN_F      512
#define OUT_F     512
#define B_ROWS    16384
#define NUM_BASIS 10
#define NFEAT     19                  // 1 silu + 8 spline + 10 logistic
#define KTOT      (NFEAT * IN_F)      // 9728

// ---------------- GEMM tiling ----------------
#define BM 128
#define BN 128
#define BK 64
#define NC (KTOT / BK)                // 152
#define STAGES 3
#define TILE_BYTES (BM * BK * 2)      // 16384 (A or B tile, fp16)
#define STAGE_BYTES (2 * TILE_BYTES)  // 32768
#define SMEM_TOTAL (STAGES * STAGE_BYTES)  // 98304

// ---------------- scratch (device globals; no allocation) ----------------
__device__ __align__(1024) __half g_F[(size_t)B_ROWS * KTOT];   // 318 MB
__device__ __align__(1024) __half g_W[(size_t)OUT_F * KTOT];    // 10 MB
__device__ __align__(16) float g_tc1[NUM_BASIS * IN_F];         // 0.5*a        [n][i]
__device__ __align__(16) float g_tc2[NUM_BASIS * IN_F];         // -0.5*a*b     [n][i]

// ---------------- PTX helpers ----------------
__device__ __forceinline__ uint32_t smem_u32(const void* p) {
    uint32_t a;
    asm("{ .reg .u64 t; cvta.to.shared.u64 t, %1; cvt.u32.u64 %0, t; }" : "=r"(a) : "l"(p));
    return a;
}
__device__ __forceinline__ void cp_async16(uint32_t dst, const void* src) {
    asm volatile("cp.async.cg.shared.global [%0], [%1], 16;" :: "r"(dst), "l"(src) : "memory");
}
__device__ __forceinline__ void cp_commit() {
    asm volatile("cp.async.commit_group;" ::: "memory");
}
template <int N>
__device__ __forceinline__ void cp_wait() {
    asm volatile("cp.async.wait_group %0;" :: "n"(N) : "memory");
}
__device__ __forceinline__ void ldmatrix_x4(uint32_t* r, uint32_t addr) {
    asm volatile("ldmatrix.sync.aligned.m8n8.x4.shared.b16 {%0, %1, %2, %3}, [%4];"
                 : "=r"(r[0]), "=r"(r[1]), "=r"(r[2]), "=r"(r[3]) : "r"(addr));
}
__device__ __forceinline__ void mma_16816(float* d, const uint32_t* a, uint32_t b0, uint32_t b1) {
    asm volatile(
        "mma.sync.aligned.m16n8k16.row.col.f32.f16.f16.f32 "
        "{%0, %1, %2, %3}, {%4, %5, %6, %7}, {%8, %9}, {%0, %1, %2, %3};"
        : "+f"(d[0]), "+f"(d[1]), "+f"(d[2]), "+f"(d[3])
        : "r"(a[0]), "r"(a[1]), "r"(a[2]), "r"(a[3]), "r"(b0), "r"(b1));
}
__device__ __forceinline__ float tanhf_approx(float z) {
    float r; asm("tanh.approx.f32 %0, %1;" : "=f"(r) : "f"(z)); return r;
}

// ---------------- tc-table init (tiny; the ONLY producer featgen depends on) ----------------
__global__ void __launch_bounds__(512) tables_kernel(const float* __restrict__ a,
                                                     const float* __restrict__ b) {
    for (int idx = blockIdx.x * 512 + threadIdx.x; idx < IN_F * NUM_BASIS;
         idx += gridDim.x * 512) {
        const int i = idx / NUM_BASIS;      // a,b are [i][n] row-major
        const int n = idx - i * NUM_BASIS;
        const float av = a[idx];
        const float bv = b[idx];
        g_tc1[n * IN_F + i] = 0.5f * av;
        g_tc2[n * IN_F + i] = -0.5f * av * bv;
    }
}

// ---------------- feature generation ----------------
#define FG_ROWS 32
#define SP_STRIDE 36   // halves per thread staging slot

__device__ __forceinline__ void store_quad(__half* p, const float* v) {
    __half2 lo = __floats2half2_rn(v[0], v[1]);
    __half2 hi = __floats2half2_rn(v[2], v[3]);
    uint2 q;
    q.x = *reinterpret_cast<uint32_t*>(&lo);
    q.y = *reinterpret_cast<uint32_t*>(&hi);
    *reinterpret_cast<uint2*>(p) = q;
}

__global__ void __launch_bounds__(256, 4) featgen_kernel(const float* __restrict__ x) {
    __shared__ __half s_sp[256 * SP_STRIDE];   // 18 KB spline scatter staging
    const int tid = threadIdx.x;

    const int iq   = (tid & 127) * 4;   // 4 consecutive input features per thread
    const int rsub = tid >> 7;          // 0..1
    __half* const myslot = s_sp + tid * SP_STRIDE;
    uint2* const myslot8 = reinterpret_cast<uint2*>(myslot);

    for (int rr = 0; rr < FG_ROWS; rr += 2) {
        const int bb = blockIdx.x * FG_ROWS + rr + rsub;
        const float4 xv = *reinterpret_cast<const float4*>(x + (size_t)bb * IN_F + iq);
        float xs[4] = {xv.x, xv.y, xv.z, xv.w};
        __half* dst = g_F + (size_t)bb * KTOT + iq;

        // ---- f = 0 : silu(x) = 0.5x + 0.5x*tanh(0.5x) ----
        {
            float v[4];
#pragma unroll
            for (int l = 0; l < 4; l++) {
                float hx = 0.5f * xs[l];
                v[l] = fmaf(hx, tanhf_approx(hx), hx);
            }
            store_quad(dst, v);
        }

        // ---- f = 1..8 : cubic B-spline bases via smem scatter staging ----
        {
#pragma unroll
            for (int j = 0; j < 8; j++) myslot8[j] = make_uint2(0u, 0u);

#pragma unroll
            for (int l = 0; l < 4; l++) {
                float u  = (xs[l] + 1.0f) * 2.5f;    // (x - GRID_LO)/h
                float fc = floorf(u);
                float t  = u - fc;
                const int c = (int)fc;
                float t2 = t * t, t3 = t2 * t;
                float om = 1.0f - t;
                float w[4];
                w[0] = om * om * om * (1.0f / 6.0f);
                w[1] = 0.5f * t3 - t2 + (2.0f / 3.0f);
                w[2] = ((-0.5f * t + 0.5f) * t + 0.5f) * t + (1.0f / 6.0f);
                w[3] = t3 * (1.0f / 6.0f);
#pragma unroll
                for (int d = 0; d < 4; d++) {
                    const int jj = c + d;
                    if ((unsigned)jj < 8u)
                        myslot[jj * 4 + l] = __float2half_rn(w[d]);
                }
            }
#pragma unroll
            for (int j = 0; j < 8; j++) {
                uint2 q = myslot8[j];
                *reinterpret_cast<uint2*>(dst + (size_t)(1 + j) * IN_F) = q;
            }
        }

        // ---- f = 9..18 : logistic  2*sigmoid(a(x-b)) = 1 + tanh(0.5a*x - 0.5ab) ----
#pragma unroll
        for (int n = 0; n < NUM_BASIS; n++) {
            const float4 c1v = *reinterpret_cast<const float4*>(&g_tc1[n * IN_F + iq]);
            const float4 c2v = *reinterpret_cast<const float4*>(&g_tc2[n * IN_F + iq]);
            float v[4];
            v[0] = 1.0f + tanhf_approx(fmaf(c1v.x, xs[0], c2v.x));
            v[1] = 1.0f + tanhf_approx(fmaf(c1v.y, xs[1], c2v.y));
            v[2] = 1.0f + tanhf_approx(fmaf(c1v.z, xs[2], c2v.z));
            v[3] = 1.0f + tanhf_approx(fmaf(c1v.w, xs[3], c2v.w));
            store_quad(dst + (size_t)(9 + n) * IN_F, v);
        }
    }
}

// ---------------- weight packing (weights only; overlaps featgen on side stream) ----------------
__global__ void __launch_bounds__(512) packw_kernel(const float* __restrict__ bw,
                                                    const float* __restrict__ sw,
                                                    const float* __restrict__ ss,
                                                    const float* __restrict__ lw,
                                                    const float* __restrict__ ls) {
    const int o = blockIdx.x;
    const int i = threadIdx.x;
    const float lsv = ls[o];
    __half* dst = g_W + (size_t)o * KTOT + i;
#pragma unroll
    for (int f = 0; f < NFEAT; f++) {
        float w;
        if (f == 0)
            w = bw[o * IN_F + i];
        else if (f <= 8)
            w = sw[((size_t)(o * IN_F + i)) * 8 + (f - 1)] * ss[o * IN_F + i];
        else
            w = lw[(size_t)o * (IN_F * NUM_BASIS) + i * NUM_BASIS + (f - 9)] * lsv;
        dst[(size_t)f * IN_F] = __float2half_rn(w);
    }
}

// ---------------- GEMM: out[16384,512] = F @ W^T ----------------
// 128 threads / 4 warps, 2x2 warp layout, 64x64 warp tiles (best-measured config).
__device__ __forceinline__ void load_stage_gemm(uint32_t sbase, int c, int tid,
                                                const __half* Asrc, const __half* Bsrc) {
    const int s = c % STAGES;
    const uint32_t ab = sbase + (uint32_t)s * STAGE_BYTES;
    const uint32_t bbuf = ab + TILE_BYTES;
    const int k0 = c * BK;
#pragma unroll
    for (int j = 0; j < 8; j++) {
        const int u = tid + j * 128;          // 1024 16B units per tile
        const int row = u >> 3;
        const int cc = u & 7;
        const uint32_t soff = (uint32_t)row * 128 + (uint32_t)((cc ^ (row & 7)) << 4);
        cp_async16(ab + soff,   Asrc + (size_t)row * KTOT + k0 + cc * 8);
        cp_async16(bbuf + soff, Bsrc + (size_t)row * KTOT + k0 + cc * 8);
    }
    cp_commit();
}

__global__ void __launch_bounds__(128, 2) gemm_kernel(float* __restrict__ out) {
    extern __shared__ __align__(128) char smem_raw[];
    const uint32_t sbase = smem_u32(smem_raw);

    const int tid  = threadIdx.x;
    const int wid  = tid >> 5;
    const int lane = tid & 31;
    const int m0 = blockIdx.y * BM;
    const int n0 = blockIdx.x * BN;
    const int wm = (wid & 1) * 64;
    const int wn = (wid >> 1) * 64;

    const __half* Asrc = g_F + (size_t)m0 * KTOT;
    const __half* Bsrc = g_W + (size_t)n0 * KTOT;

    float acc[4][8][4];
#pragma unroll
    for (int mt = 0; mt < 4; mt++)
#pragma unroll
        for (int nt = 0; nt < 8; nt++)
#pragma unroll
            for (int q = 0; q < 4; q++) acc[mt][nt][q] = 0.0f;

    const int a_row_l = lane & 15;
    const int a_ch_l  = lane >> 4;
    const int b_row_l = (lane & 7) + ((lane >> 4) << 3);
    const int b_ch_l  = (lane >> 3) & 1;

    load_stage_gemm(sbase, 0, tid, Asrc, Bsrc);
    load_stage_gemm(sbase, 1, tid, Asrc, Bsrc);

#pragma unroll 1
    for (int c = 0; c < NC; c++) {
        if (c < NC - 1) cp_wait<1>(); else cp_wait<0>();
        __syncthreads();
        if (c + 2 < NC) load_stage_gemm(sbase, c + 2, tid, Asrc, Bsrc);

        const uint32_t abase = sbase + (uint32_t)(c % STAGES) * STAGE_BYTES;
        const uint32_t bbase = abase + TILE_BYTES;

#pragma unroll
        for (int ks = 0; ks < 4; ks++) {
            uint32_t afr[4][4];
#pragma unroll
            for (int mt = 0; mt < 4; mt++) {
                const int row = wm + mt * 16 + a_row_l;
                const int ch = ks * 2 + a_ch_l;
                ldmatrix_x4(afr[mt], abase + (uint32_t)row * 128
                                         + (uint32_t)((ch ^ (row & 7)) << 4));
            }
            uint32_t bfr[4][4];
#pragma unroll
            for (int np = 0; np < 4; np++) {
                const int row = wn + np * 16 + b_row_l;
                const int ch = ks * 2 + b_ch_l;
                ldmatrix_x4(bfr[np], bbase + (uint32_t)row * 128
                                         + (uint32_t)((ch ^ (row & 7)) << 4));
            }
#pragma unroll
            for (int mt = 0; mt < 4; mt++)
#pragma unroll
                for (int nt = 0; nt < 8; nt++)
                    mma_16816(acc[mt][nt], afr[mt],
                              bfr[nt >> 1][(nt & 1) * 2 + 0],
                              bfr[nt >> 1][(nt & 1) * 2 + 1]);
        }
    }

    // epilogue: direct fp32 stores
#pragma unroll
    for (int mt = 0; mt < 4; mt++) {
#pragma unroll
        for (int nt = 0; nt < 8; nt++) {
            const int m = m0 + wm + mt * 16 + (lane >> 2);
            const int n = n0 + wn + nt * 8 + (lane & 3) * 2;
            float2 v0 = make_float2(acc[mt][nt][0], acc[mt][nt][1]);
            float2 v1 = make_float2(acc[mt][nt][2], acc[mt][nt][3]);
            *reinterpret_cast<float2*>(out + (size_t)m * OUT_F + n) = v0;
            *reinterpret_cast<float2*>(out + (size_t)(m + 8) * OUT_F + n) = v1;
        }
    }
}

// ---------------- launch: serial featgen->gemm; packw overlapped with featgen ----------------
extern "C" void kernel_launch(void* const* d_in, const int* in_sizes, int n_in,
                              void* d_out, int out_size) {
    const float* x  = (const float*)d_in[0];
    const float* bw = (const float*)d_in[1];
    const float* sw = (const float*)d_in[2];
    const float* ss = (const float*)d_in[3];
    const float* a  = (const float*)d_in[4];
    const float* b  = (const float*)d_in[5];
    const float* lw = (const float*)d_in[6];
    const float* ls = (const float*)d_in[7];
    float* out = (float*)d_out;

    static cudaStream_t s2 = nullptr;
    static cudaEvent_t ev_fork = nullptr, ev_pw = nullptr;
    if (s2 == nullptr) {
        cudaStreamCreateWithFlags(&s2, cudaStreamNonBlocking);
        cudaEventCreateWithFlags(&ev_fork, cudaEventDisableTiming);
        cudaEventCreateWithFlags(&ev_pw, cudaEventDisableTiming);
        cudaFuncSetAttribute(gemm_kernel, cudaFuncAttributeMaxDynamicSharedMemorySize,
                             SMEM_TOTAL);
    }

    // stream 0: tiny table init (the only thing featgen depends on), then featgen
    tables_kernel<<<10, 512>>>(a, b);
    cudaEventRecord(ev_fork, 0);
    featgen_kernel<<<B_ROWS / FG_ROWS, 256>>>(x);

    // side stream: weight packing, concurrent with featgen (gemm needs it, featgen doesn't)
    cudaStreamWaitEvent(s2, ev_fork, 0);
    packw_kernel<<<OUT_F, 512, 0, s2>>>(bw, sw, ss, lw, ls);
    cudaEventRecord(ev_pw, s2);

    // stream 0: gemm after featgen (program order) AND packw (event)
    cudaStreamWaitEvent(0, ev_pw, 0);
    dim3 grid(OUT_F / BN, B_ROWS / BM);   // x = n (4, fast), y = m (128)
    gemm_kernel<<<grid, 128, SMEM_TOTAL>>>(out);
}

// round 17
// speedup vs baseline: 1.5886x; 1.0172x over previous
#include <cuda_runtime.h>
#include <cuda_fp16.h>
#include <cstdint>
#include <cstddef>

// ---------------- problem constants ----------------
#define IN_F      512
#define OUT_F     512
#define B_ROWS    16384
#define NUM_BASIS 10
#define NFEAT     19                  // 1 silu + 8 spline + 10 logistic
#define KTOT      (NFEAT * IN_F)      // 9728

// ---------------- GEMM tiling ----------------
#define BM 128
#define BN 128
#define BK 64
#define NC (KTOT / BK)                // 152 chunks total
#define KSPLIT 4
#define NCQ (NC / KSPLIT)             // 38 chunks per K-quarter unit
#define NTILES ((B_ROWS / BM) * (OUT_F / BN))   // 512
#define STAGES 3
#define TILE_BYTES (BM * BK * 2)      // 16384 (A or B tile, fp16)
#define STAGE_BYTES (2 * TILE_BYTES)  // 32768
#define SMEM_TOTAL (STAGES * STAGE_BYTES)  // 98304

// ---------------- scratch (device globals; no allocation) ----------------
__device__ __align__(1024) __half g_F[(size_t)B_ROWS * KTOT];   // 318 MB
__device__ __align__(1024) __half g_W[(size_t)OUT_F * KTOT];    // 10 MB
__device__ __align__(16) float g_tc1[NUM_BASIS * IN_F];         // 0.5*a        [n][i]
__device__ __align__(16) float g_tc2[NUM_BASIS * IN_F];         // -0.5*a*b     [n][i]
__device__ __align__(1024) float g_part[KSPLIT][(size_t)B_ROWS * OUT_F];  // 134 MB
__device__ unsigned int g_cnt[NTILES];

// ---------------- PTX helpers ----------------
__device__ __forceinline__ uint32_t smem_u32(const void* p) {
    uint32_t a;
    asm("{ .reg .u64 t; cvta.to.shared.u64 t, %1; cvt.u32.u64 %0, t; }" : "=r"(a) : "l"(p));
    return a;
}
__device__ __forceinline__ void cp_async16(uint32_t dst, const void* src) {
    asm volatile("cp.async.cg.shared.global [%0], [%1], 16;" :: "r"(dst), "l"(src) : "memory");
}
__device__ __forceinline__ void cp_commit() {
    asm volatile("cp.async.commit_group;" ::: "memory");
}
template <int N>
__device__ __forceinline__ void cp_wait() {
    asm volatile("cp.async.wait_group %0;" :: "n"(N) : "memory");
}
__device__ __forceinline__ void ldmatrix_x4(uint32_t* r, uint32_t addr) {
    asm volatile("ldmatrix.sync.aligned.m8n8.x4.shared.b16 {%0, %1, %2, %3}, [%4];"
                 : "=r"(r[0]), "=r"(r[1]), "=r"(r[2]), "=r"(r[3]) : "r"(addr));
}
__device__ __forceinline__ void mma_16816(float* d, const uint32_t* a, uint32_t b0, uint32_t b1) {
    asm volatile(
        "mma.sync.aligned.m16n8k16.row.col.f32.f16.f16.f32 "
        "{%0, %1, %2, %3}, {%4, %5, %6, %7}, {%8, %9}, {%0, %1, %2, %3};"
        : "+f"(d[0]), "+f"(d[1]), "+f"(d[2]), "+f"(d[3])
        : "r"(a[0]), "r"(a[1]), "r"(a[2]), "r"(a[3]), "r"(b0), "r"(b1));
}
__device__ __forceinline__ float tanhf_approx(float z) {
    float r; asm("tanh.approx.f32 %0, %1;" : "=f"(r) : "f"(z)); return r;
}

// ---------------- tc-table init + split-K counter reset ----------------
__global__ void __launch_bounds__(512) tables_kernel(const float* __restrict__ a,
                                                     const float* __restrict__ b) {
    const int t0 = blockIdx.x * 512 + threadIdx.x;
    for (int idx = t0; idx < IN_F * NUM_BASIS; idx += gridDim.x * 512) {
        const int i = idx / NUM_BASIS;      // a,b are [i][n] row-major
        const int n = idx - i * NUM_BASIS;
        const float av = a[idx];
        const float bv = b[idx];
        g_tc1[n * IN_F + i] = 0.5f * av;
        g_tc2[n * IN_F + i] = -0.5f * av * bv;
    }
    for (int idx = t0; idx < NTILES; idx += gridDim.x * 512)
        g_cnt[idx] = 0u;
}

// ---------------- feature generation ----------------
#define FG_ROWS 32
#define SP_STRIDE 36   // halves per thread staging slot

__device__ __forceinline__ void store_quad(__half* p, const float* v) {
    __half2 lo = __floats2half2_rn(v[0], v[1]);
    __half2 hi = __floats2half2_rn(v[2], v[3]);
    uint2 q;
    q.x = *reinterpret_cast<uint32_t*>(&lo);
    q.y = *reinterpret_cast<uint32_t*>(&hi);
    *reinterpret_cast<uint2*>(p) = q;
}

__global__ void __launch_bounds__(256, 4) featgen_kernel(const float* __restrict__ x) {
    __shared__ __half s_sp[256 * SP_STRIDE];   // 18 KB spline scatter staging
    const int tid = threadIdx.x;

    const int iq   = (tid & 127) * 4;   // 4 consecutive input features per thread
    const int rsub = tid >> 7;          // 0..1
    __half* const myslot = s_sp + tid * SP_STRIDE;
    uint2* const myslot8 = reinterpret_cast<uint2*>(myslot);

    for (int rr = 0; rr < FG_ROWS; rr += 2) {
        const int bb = blockIdx.x * FG_ROWS + rr + rsub;
        const float4 xv = *reinterpret_cast<const float4*>(x + (size_t)bb * IN_F + iq);
        float xs[4] = {xv.x, xv.y, xv.z, xv.w};
        __half* dst = g_F + (size_t)bb * KTOT + iq;

        // ---- f = 0 : silu(x) = 0.5x + 0.5x*tanh(0.5x) ----
        {
            float v[4];
#pragma unroll
            for (int l = 0; l < 4; l++) {
                float hx = 0.5f * xs[l];
                v[l] = fmaf(hx, tanhf_approx(hx), hx);
            }
            store_quad(dst, v);
        }

        // ---- f = 1..8 : cubic B-spline bases via smem scatter staging ----
        {
#pragma unroll
            for (int j = 0; j < 8; j++) myslot8[j] = make_uint2(0u, 0u);

#pragma unroll
            for (int l = 0; l < 4; l++) {
                float u  = (xs[l] + 1.0f) * 2.5f;    // (x - GRID_LO)/h
                float fc = floorf(u);
                float t  = u - fc;
                const int c = (int)fc;
                float t2 = t * t, t3 = t2 * t;
                float om = 1.0f - t;
                float w[4];
                w[0] = om * om * om * (1.0f / 6.0f);
                w[1] = 0.5f * t3 - t2 + (2.0f / 3.0f);
                w[2] = ((-0.5f * t + 0.5f) * t + 0.5f) * t + (1.0f / 6.0f);
                w[3] = t3 * (1.0f / 6.0f);
#pragma unroll
                for (int d = 0; d < 4; d++) {
                    const int jj = c + d;
                    if ((unsigned)jj < 8u)
                        myslot[jj * 4 + l] = __float2half_rn(w[d]);
                }
            }
#pragma unroll
            for (int j = 0; j < 8; j++) {
                uint2 q = myslot8[j];
                *reinterpret_cast<uint2*>(dst + (size_t)(1 + j) * IN_F) = q;
            }
        }

        // ---- f = 9..18 : logistic  2*sigmoid(a(x-b)) = 1 + tanh(0.5a*x - 0.5ab) ----
#pragma unroll
        for (int n = 0; n < NUM_BASIS; n++) {
            const float4 c1v = *reinterpret_cast<const float4*>(&g_tc1[n * IN_F + iq]);
            const float4 c2v = *reinterpret_cast<const float4*>(&g_tc2[n * IN_F + iq]);
            float v[4];
            v[0] = 1.0f + tanhf_approx(fmaf(c1v.x, xs[0], c2v.x));
            v[1] = 1.0f + tanhf_approx(fmaf(c1v.y, xs[1], c2v.y));
            v[2] = 1.0f + tanhf_approx(fmaf(c1v.z, xs[2], c2v.z));
            v[3] = 1.0f + tanhf_approx(fmaf(c1v.w, xs[3], c2v.w));
            store_quad(dst + (size_t)(9 + n) * IN_F, v);
        }
    }
}

// ---------------- weight packing (weights only; overlaps featgen on side stream) ----------------
__global__ void __launch_bounds__(512) packw_kernel(const float* __restrict__ bw,
                                                    const float* __restrict__ sw,
                                                    const float* __restrict__ ss,
                                                    const float* __restrict__ lw,
                                                    const float* __restrict__ ls) {
    const int o = blockIdx.x;
    const int i = threadIdx.x;
    const float lsv = ls[o];
    __half* dst = g_W + (size_t)o * KTOT + i;
#pragma unroll
    for (int f = 0; f < NFEAT; f++) {
        float w;
        if (f == 0)
            w = bw[o * IN_F + i];
        else if (f <= 8)
            w = sw[((size_t)(o * IN_F + i)) * 8 + (f - 1)] * ss[o * IN_F + i];
        else
            w = lw[(size_t)o * (IN_F * NUM_BASIS) + i * NUM_BASIS + (f - 9)] * lsv;
        dst[(size_t)f * IN_F] = __float2half_rn(w);
    }
}

// ---------------- GEMM: split-K=4 partials + fused last-CTA reduction ----------------
// 128 threads / 4 warps, 2x2 warp layout, 64x64 warp tiles.
__device__ __forceinline__ void load_stage_gemm(uint32_t sbase, int c, int kbase, int tid,
                                                const __half* Asrc, const __half* Bsrc) {
    const int s = c % STAGES;
    const uint32_t ab = sbase + (uint32_t)s * STAGE_BYTES;
    const uint32_t bbuf = ab + TILE_BYTES;
    const int k0 = (kbase + c) * BK;
#pragma unroll
    for (int j = 0; j < 8; j++) {
        const int u = tid + j * 128;          // 1024 16B units per tile
        const int row = u >> 3;
        const int cc = u & 7;
        const uint32_t soff = (uint32_t)row * 128 + (uint32_t)((cc ^ (row & 7)) << 4);
        cp_async16(ab + soff,   Asrc + (size_t)row * KTOT + k0 + cc * 8);
        cp_async16(bbuf + soff, Bsrc + (size_t)row * KTOT + k0 + cc * 8);
    }
    cp_commit();
}

__global__ void __launch_bounds__(128, 2) gemm_kernel(float* __restrict__ out) {
    extern __shared__ __align__(128) char smem_raw[];
    const uint32_t sbase = smem_u32(smem_raw);
    __shared__ unsigned int s_old;

    const int tid  = threadIdx.x;
    const int wid  = tid >> 5;
    const int lane = tid & 31;
    const int m0 = blockIdx.y * BM;
    const int n0 = blockIdx.x * BN;
    const int zq = blockIdx.z;               // K-quarter
    const int kbase = zq * NCQ;
    const int tile = blockIdx.y * (OUT_F / BN) + blockIdx.x;
    const int wm = (wid & 1) * 64;
    const int wn = (wid >> 1) * 64;

    const __half* Asrc = g_F + (size_t)m0 * KTOT;
    const __half* Bsrc = g_W + (size_t)n0 * KTOT;
    float* pout = g_part[zq];

    float acc[4][8][4];
#pragma unroll
    for (int mt = 0; mt < 4; mt++)
#pragma unroll
        for (int nt = 0; nt < 8; nt++)
#pragma unroll
            for (int q = 0; q < 4; q++) acc[mt][nt][q] = 0.0f;

    const int a_row_l = lane & 15;
    const int a_ch_l  = lane >> 4;
    const int b_row_l = (lane & 7) + ((lane >> 4) << 3);
    const int b_ch_l  = (lane >> 3) & 1;

    load_stage_gemm(sbase, 0, kbase, tid, Asrc, Bsrc);
    load_stage_gemm(sbase, 1, kbase, tid, Asrc, Bsrc);

#pragma unroll 1
    for (int c = 0; c < NCQ; c++) {
        if (c < NCQ - 1) cp_wait<1>(); else cp_wait<0>();
        __syncthreads();
        if (c + 2 < NCQ) load_stage_gemm(sbase, c + 2, kbase, tid, Asrc, Bsrc);

        const uint32_t abase = sbase + (uint32_t)(c % STAGES) * STAGE_BYTES;
        const uint32_t bbase = abase + TILE_BYTES;

#pragma unroll
        for (int ks = 0; ks < 4; ks++) {
            uint32_t afr[4][4];
#pragma unroll
            for (int mt = 0; mt < 4; mt++) {
                const int row = wm + mt * 16 + a_row_l;
                const int ch = ks * 2 + a_ch_l;
                ldmatrix_x4(afr[mt], abase + (uint32_t)row * 128
                                         + (uint32_t)((ch ^ (row & 7)) << 4));
            }
            uint32_t bfr[4][4];
#pragma unroll
            for (int np = 0; np < 4; np++) {
                const int row = wn + np * 16 + b_row_l;
                const int ch = ks * 2 + b_ch_l;
                ldmatrix_x4(bfr[np], bbase + (uint32_t)row * 128
                                         + (uint32_t)((ch ^ (row & 7)) << 4));
            }
#pragma unroll
            for (int mt = 0; mt < 4; mt++)
#pragma unroll
                for (int nt = 0; nt < 8; nt++)
                    mma_16816(acc[mt][nt], afr[mt],
                              bfr[nt >> 1][(nt & 1) * 2 + 0],
                              bfr[nt >> 1][(nt & 1) * 2 + 1]);
        }
    }

    // store partial for this K-quarter
#pragma unroll
    for (int mt = 0; mt < 4; mt++) {
#pragma unroll
        for (int nt = 0; nt < 8; nt++) {
            const int m = m0 + wm + mt * 16 + (lane >> 2);
            const int n = n0 + wn + nt * 8 + (lane & 3) * 2;
            float2 v0 = make_float2(acc[mt][nt][0], acc[mt][nt][1]);
            float2 v1 = make_float2(acc[mt][nt][2], acc[mt][nt][3]);
            *reinterpret_cast<float2*>(pout + (size_t)m * OUT_F + n) = v0;
            *reinterpret_cast<float2*>(pout + (size_t)(m + 8) * OUT_F + n) = v1;
        }
    }

    // last unit of this tile sums all 4 partials in FIXED z order (deterministic)
    __threadfence();
    if (tid == 0) s_old = atomicAdd(&g_cnt[tile], 1u);
    __syncthreads();
    if (s_old == KSPLIT - 1) {
        const int row = m0 + tid;    // 128 threads, one row each
        const size_t off = (size_t)row * OUT_F + n0;
        const float4* p0 = reinterpret_cast<const float4*>(g_part[0] + off);
        const float4* p1 = reinterpret_cast<const float4*>(g_part[1] + off);
        const float4* p2 = reinterpret_cast<const float4*>(g_part[2] + off);
        const float4* p3 = reinterpret_cast<const float4*>(g_part[3] + off);
        float4* o4 = reinterpret_cast<float4*>(out + off);
#pragma unroll 4
        for (int j = 0; j < BN / 4; j++) {
            float4 a0 = p0[j], a1 = p1[j], a2 = p2[j], a3 = p3[j];
            float4 s;
            s.x = ((a0.x + a1.x) + a2.x) + a3.x;
            s.y = ((a0.y + a1.y) + a2.y) + a3.y;
            s.z = ((a0.z + a1.z) + a2.z) + a3.z;
            s.w = ((a0.w + a1.w) + a2.w) + a3.w;
            o4[j] = s;
        }
    }
}

// ---------------- launch: serial featgen->gemm; packw overlapped with featgen ----------------
extern "C" void kernel_launch(void* const* d_in, const int* in_sizes, int n_in,
                              void* d_out, int out_size) {
    const float* x  = (const float*)d_in[0];
    const float* bw = (const float*)d_in[1];
    const float* sw = (const float*)d_in[2];
    const float* ss = (const float*)d_in[3];
    const float* a  = (const float*)d_in[4];
    const float* b  = (const float*)d_in[5];
    const float* lw = (const float*)d_in[6];
    const float* ls = (const float*)d_in[7];
    float* out = (float*)d_out;

    static cudaStream_t s2 = nullptr;
    static cudaEvent_t ev_fork = nullptr, ev_pw = nullptr;
    if (s2 == nullptr) {
        cudaStreamCreateWithFlags(&s2, cudaStreamNonBlocking);
        cudaEventCreateWithFlags(&ev_fork, cudaEventDisableTiming);
        cudaEventCreateWithFlags(&ev_pw, cudaEventDisableTiming);
        cudaFuncSetAttribute(gemm_kernel, cudaFuncAttributeMaxDynamicSharedMemorySize,
                             SMEM_TOTAL);
    }

    // stream 0: table init + counter reset (featgen/gemm prerequisites), then featgen
    tables_kernel<<<10, 512>>>(a, b);
    cudaEventRecord(ev_fork, 0);
    featgen_kernel<<<B_ROWS / FG_ROWS, 256>>>(x);

    // side stream: weight packing, concurrent with featgen (gemm needs it, featgen doesn't)
    cudaStreamWaitEvent(s2, ev_fork, 0);
    packw_kernel<<<OUT_F, 512, 0, s2>>>(bw, sw, ss, lw, ls);
    cudaEventRecord(ev_pw, s2);

    // stream 0: gemm after featgen (program order) AND packw (event)
    cudaStreamWaitEvent(0, ev_pw, 0);
    dim3 grid(OUT_F / BN, B_ROWS / BM, KSPLIT);   // (4, 128, 4) = 2048 units
    gemm_kernel<<<grid, 128, SMEM_TOTAL>>>(out);
}